// round 2
// baseline (speedup 1.0000x reference)
#include <cuda_runtime.h>

// GlobalFilter: y = irfft(rfft(x, axis=-1) * w, n=10, axis=-1)
// x: [B, DIM, 10] f32, w: [DIM, 6, 2] f32 -> y: [B, DIM, 10] f32
//
// Per row (b,d): linear map. Split-radix over N=10:
//   u_s = x_s + x_{s+5}, v_s = x_s - x_{s+5}  (s=0..4)
//   even bins k=0,2,4 from 5-pt DFT of u; odd bins k=1,3,5 from 5-pt DFT of v.
//   Z_k = X_k * w_k;  y_t = 0.1*Re(Z0) + 0.1*(-1)^t*Re(Z5)
//                         + 0.2*sum_{k=1..4}(Zr_k cos(wkt) - Zi_k sin(wkt))
//   with y_t = E_t + O_t, y_{t+5} = E_t - O_t  (t=0..4).
// ducc/pocketfft c2r ignores Im of DC & Nyquist — matched by using Re(Z0), Re(Z5).

#define THREADS 256
#define ROWS_PER_BLOCK 256
#define NPTS 10

// cos/sin(2*pi*j/10), j = 0..9
__device__ __constant__ const float kC[10] = {
    1.0f,  0.80901699437494745f,  0.30901699437494745f, -0.30901699437494745f,
    -0.80901699437494745f, -1.0f, -0.80901699437494745f, -0.30901699437494745f,
    0.30901699437494745f,  0.80901699437494745f
};
__device__ __constant__ const float kS[10] = {
    0.0f,  0.58778525229247314f,  0.95105651629515353f,  0.95105651629515353f,
    0.58778525229247314f,  0.0f, -0.58778525229247314f, -0.95105651629515353f,
    -0.95105651629515353f, -0.58778525229247314f
};

// Compile-time twiddle helpers (constexpr -> immediates in SASS)
__host__ __device__ constexpr float ctC(int j) {
    const float t[10] = {1.0f, 0.80901699437494745f, 0.30901699437494745f,
                         -0.30901699437494745f, -0.80901699437494745f, -1.0f,
                         -0.80901699437494745f, -0.30901699437494745f,
                         0.30901699437494745f, 0.80901699437494745f};
    return t[j % 10];
}
__host__ __device__ constexpr float ctS(int j) {
    const float t[10] = {0.0f, 0.58778525229247314f, 0.95105651629515353f,
                         0.95105651629515353f, 0.58778525229247314f, 0.0f,
                         -0.58778525229247314f, -0.95105651629515353f,
                         -0.95105651629515353f, -0.58778525229247314f};
    return t[j % 10];
}

__global__ __launch_bounds__(THREADS)
void global_filter_kernel(const float* __restrict__ x,
                          const float* __restrict__ w,
                          float* __restrict__ y,
                          int n_rows, int dim)
{
    __shared__ float sx[ROWS_PER_BLOCK * NPTS];   // 10240 B

    const int tid  = threadIdx.x;
    const int row0 = blockIdx.x * ROWS_PER_BLOCK;
    const int rows_here = min(ROWS_PER_BLOCK, n_rows - row0);
    const int elems = rows_here * NPTS;
    const long long base = (long long)row0 * NPTS;   // 2560*blk -> 16B aligned

    // ---- stage in (coalesced) ----
    if (elems == ROWS_PER_BLOCK * NPTS) {
        const float4* gx4 = reinterpret_cast<const float4*>(x + base);
        float4* sx4 = reinterpret_cast<float4*>(sx);
        #pragma unroll
        for (int i = tid; i < (ROWS_PER_BLOCK * NPTS) / 4; i += THREADS)
            sx4[i] = gx4[i];
    } else {
        for (int i = tid; i < elems; i += THREADS)
            sx[i] = x[base + i];
    }
    __syncthreads();

    if (tid < rows_here) {
        const int row = row0 + tid;
        const int d   = row % dim;

        // weights: 12 floats per dim, 16B aligned (48B stride)
        const float4* wp = reinterpret_cast<const float4*>(w + d * 12);
        const float4 w0 = wp[0];   // a0 b0 a1 b1
        const float4 w1 = wp[1];   // a2 b2 a3 b3
        const float4 w2 = wp[2];   // a4 b4 a5 b5

        // read my 10 floats (float2, 2-way bank conflict at worst)
        float xv[NPTS];
        const float2* s2 = reinterpret_cast<const float2*>(sx);
        #pragma unroll
        for (int i = 0; i < 5; ++i) {
            float2 p = s2[tid * 5 + i];
            xv[2 * i] = p.x; xv[2 * i + 1] = p.y;
        }

        // ---- forward: split into half-sums ----
        float u[5], v[5];
        #pragma unroll
        for (int s = 0; s < 5; ++s) {
            u[s] = xv[s] + xv[s + 5];
            v[s] = xv[s] - xv[s + 5];
        }

        // even bins (from u): k = 0, 2, 4
        float Xr0 = u[0] + u[1] + u[2] + u[3] + u[4];
        float Xr2 = u[0], Xi2 = 0.f, Xr4 = u[0], Xi4 = 0.f;
        #pragma unroll
        for (int s = 1; s < 5; ++s) {
            Xr2 += ctC(2 * s) * u[s];  Xi2 -= ctS(2 * s) * u[s];
            Xr4 += ctC(4 * s) * u[s];  Xi4 -= ctS(4 * s) * u[s];
        }
        // odd bins (from v): k = 1, 3, 5
        float Xr1 = v[0], Xi1 = 0.f, Xr3 = v[0], Xi3 = 0.f;
        #pragma unroll
        for (int s = 1; s < 5; ++s) {
            Xr1 += ctC(1 * s) * v[s];  Xi1 -= ctS(1 * s) * v[s];
            Xr3 += ctC(3 * s) * v[s];  Xi3 -= ctS(3 * s) * v[s];
        }
        float Xr5 = v[0] - v[1] + v[2] - v[3] + v[4];

        // ---- pointwise multiply by w, with inverse scaling folded in ----
        const float a1 = w0.z, b1 = w0.w;
        const float a2 = w1.x, b2 = w1.y;
        const float a3 = w1.z, b3 = w1.w;
        const float a4 = w2.x, b4 = w2.y;
        const float Zr0 = 0.1f * (Xr0 * w0.x);          // a0; Xi0 == 0
        const float Zr5 = 0.1f * (Xr5 * w2.z);          // a5; Xi5 == 0
        const float zr1 = 0.2f * (Xr1 * a1 - Xi1 * b1);
        const float zi1 = 0.2f * (Xr1 * b1 + Xi1 * a1);
        const float zr2 = 0.2f * (Xr2 * a2 - Xi2 * b2);
        const float zi2 = 0.2f * (Xr2 * b2 + Xi2 * a2);
        const float zr3 = 0.2f * (Xr3 * a3 - Xi3 * b3);
        const float zi3 = 0.2f * (Xr3 * b3 + Xi3 * a3);
        const float zr4 = 0.2f * (Xr4 * a4 - Xi4 * b4);
        const float zi4 = 0.2f * (Xr4 * b4 + Xi4 * a4);

        // ---- inverse: E/O split, y_t = E+O, y_{t+5} = E-O ----
        float yv[NPTS];
        #pragma unroll
        for (int t = 0; t < 5; ++t) {
            float E = Zr0
                    + zr2 * ctC(2 * t) - zi2 * ctS(2 * t)
                    + zr4 * ctC(4 * t) - zi4 * ctS(4 * t);
            float O = ((t & 1) ? -Zr5 : Zr5)
                    + zr1 * ctC(t)     - zi1 * ctS(t)
                    + zr3 * ctC(3 * t) - zi3 * ctS(3 * t);
            yv[t]     = E + O;
            yv[t + 5] = E - O;
        }

        // write back in place (thread owns its own slots — no sync needed here)
        float2* s2w = reinterpret_cast<float2*>(sx);
        #pragma unroll
        for (int i = 0; i < 5; ++i) {
            float2 p; p.x = yv[2 * i]; p.y = yv[2 * i + 1];
            s2w[tid * 5 + i] = p;
        }
    }
    __syncthreads();

    // ---- stage out (coalesced) ----
    if (elems == ROWS_PER_BLOCK * NPTS) {
        float4* gy4 = reinterpret_cast<float4*>(y + base);
        const float4* sx4 = reinterpret_cast<const float4*>(sx);
        #pragma unroll
        for (int i = tid; i < (ROWS_PER_BLOCK * NPTS) / 4; i += THREADS)
            gy4[i] = sx4[i];
    } else {
        for (int i = tid; i < elems; i += THREADS)
            y[base + i] = sx[i];
    }
}

extern "C" void kernel_launch(void* const* d_in, const int* in_sizes, int n_in,
                              void* d_out, int out_size)
{
    const float* x = (const float*)d_in[0];
    const float* w = (const float*)d_in[1];
    float* y = (float*)d_out;

    const int n_rows = in_sizes[0] / NPTS;       // B * DIM
    const int dim    = in_sizes[1] / 12;         // DIM (6 freqs * 2)

    const int blocks = (n_rows + ROWS_PER_BLOCK - 1) / ROWS_PER_BLOCK;
    global_filter_kernel<<<blocks, THREADS>>>(x, w, y, n_rows, dim);
}

// round 3
// speedup vs baseline: 1.0116x; 1.0116x over previous
#include <cuda_runtime.h>

// GlobalFilter: y = irfft(rfft(x, axis=-1) * w, n=10, axis=-1)
// x: [B, DIM, 10] f32, w: [DIM, 6, 2] f32 -> y: [B, DIM, 10] f32
// Split-radix N=10 closed form; see R1 comments. R2: 512 rows/block,
// 2 rows/thread, fully-unrolled float4 staging for MLP=5.

#define THREADS 256
#define ROWS_PER_BLOCK 512            // 2 rows per thread
#define NPTS 10
#define BLK_ELEMS (ROWS_PER_BLOCK * NPTS)   // 5120 floats
#define BLK_VEC4  (BLK_ELEMS / 4)           // 1280 float4 -> 5 per thread

__host__ __device__ constexpr float ctC(int j) {
    const float t[10] = {1.0f, 0.80901699437494745f, 0.30901699437494745f,
                         -0.30901699437494745f, -0.80901699437494745f, -1.0f,
                         -0.80901699437494745f, -0.30901699437494745f,
                         0.30901699437494745f, 0.80901699437494745f};
    return t[j % 10];
}
__host__ __device__ constexpr float ctS(int j) {
    const float t[10] = {0.0f, 0.58778525229247314f, 0.95105651629515353f,
                         0.95105651629515353f, 0.58778525229247314f, 0.0f,
                         -0.58778525229247314f, -0.95105651629515353f,
                         -0.95105651629515353f, -0.58778525229247314f};
    return t[j % 10];
}

// Compute one row in-place in shared memory. ridx = row index within block.
__device__ __forceinline__ void process_row(float* sx, int ridx,
                                            const float* __restrict__ w,
                                            int d)
{
    // weights: 12 floats per dim, 16B aligned (48B stride)
    const float4* wp = reinterpret_cast<const float4*>(w + d * 12);
    const float4 w0 = wp[0];   // a0 b0 a1 b1
    const float4 w1 = wp[1];   // a2 b2 a3 b3
    const float4 w2 = wp[2];   // a4 b4 a5 b5

    float xv[NPTS];
    const float2* s2 = reinterpret_cast<const float2*>(sx);
    #pragma unroll
    for (int i = 0; i < 5; ++i) {
        float2 p = s2[ridx * 5 + i];
        xv[2 * i] = p.x; xv[2 * i + 1] = p.y;
    }

    // forward: half-sum split
    float u[5], v[5];
    #pragma unroll
    for (int s = 0; s < 5; ++s) {
        u[s] = xv[s] + xv[s + 5];
        v[s] = xv[s] - xv[s + 5];
    }

    float Xr0 = u[0] + u[1] + u[2] + u[3] + u[4];
    float Xr2 = u[0], Xi2 = 0.f, Xr4 = u[0], Xi4 = 0.f;
    #pragma unroll
    for (int s = 1; s < 5; ++s) {
        Xr2 += ctC(2 * s) * u[s];  Xi2 -= ctS(2 * s) * u[s];
        Xr4 += ctC(4 * s) * u[s];  Xi4 -= ctS(4 * s) * u[s];
    }
    float Xr1 = v[0], Xi1 = 0.f, Xr3 = v[0], Xi3 = 0.f;
    #pragma unroll
    for (int s = 1; s < 5; ++s) {
        Xr1 += ctC(1 * s) * v[s];  Xi1 -= ctS(1 * s) * v[s];
        Xr3 += ctC(3 * s) * v[s];  Xi3 -= ctS(3 * s) * v[s];
    }
    float Xr5 = v[0] - v[1] + v[2] - v[3] + v[4];

    // pointwise multiply (inverse 1/N scaling folded in)
    const float a1 = w0.z, b1 = w0.w;
    const float a2 = w1.x, b2 = w1.y;
    const float a3 = w1.z, b3 = w1.w;
    const float a4 = w2.x, b4 = w2.y;
    const float Zr0 = 0.1f * (Xr0 * w0.x);
    const float Zr5 = 0.1f * (Xr5 * w2.z);
    const float zr1 = 0.2f * (Xr1 * a1 - Xi1 * b1);
    const float zi1 = 0.2f * (Xr1 * b1 + Xi1 * a1);
    const float zr2 = 0.2f * (Xr2 * a2 - Xi2 * b2);
    const float zi2 = 0.2f * (Xr2 * b2 + Xi2 * a2);
    const float zr3 = 0.2f * (Xr3 * a3 - Xi3 * b3);
    const float zi3 = 0.2f * (Xr3 * b3 + Xi3 * a3);
    const float zr4 = 0.2f * (Xr4 * a4 - Xi4 * b4);
    const float zi4 = 0.2f * (Xr4 * b4 + Xi4 * a4);

    // inverse: E/O split
    float yv[NPTS];
    #pragma unroll
    for (int t = 0; t < 5; ++t) {
        float E = Zr0
                + zr2 * ctC(2 * t) - zi2 * ctS(2 * t)
                + zr4 * ctC(4 * t) - zi4 * ctS(4 * t);
        float O = ((t & 1) ? -Zr5 : Zr5)
                + zr1 * ctC(t)     - zi1 * ctS(t)
                + zr3 * ctC(3 * t) - zi3 * ctS(3 * t);
        yv[t]     = E + O;
        yv[t + 5] = E - O;
    }

    float2* s2w = reinterpret_cast<float2*>(sx);
    #pragma unroll
    for (int i = 0; i < 5; ++i) {
        float2 p; p.x = yv[2 * i]; p.y = yv[2 * i + 1];
        s2w[ridx * 5 + i] = p;
    }
}

__global__ __launch_bounds__(THREADS)
void global_filter_kernel(const float* __restrict__ x,
                          const float* __restrict__ w,
                          float* __restrict__ y,
                          int n_rows, int dim, int dim_mask)
{
    __shared__ float sx[BLK_ELEMS];   // 20480 B

    const int tid  = threadIdx.x;
    const int row0 = blockIdx.x * ROWS_PER_BLOCK;
    const int rows_here = min(ROWS_PER_BLOCK, n_rows - row0);
    const long long base = (long long)row0 * NPTS;   // 5120*blk -> 16B aligned

    if (rows_here == ROWS_PER_BLOCK) {
        // ---- stage in: 5 front-batched float4 LDGs per thread ----
        const float4* __restrict__ gx4 = reinterpret_cast<const float4*>(x + base);
        float4* sx4 = reinterpret_cast<float4*>(sx);
        float4 r[5];
        #pragma unroll
        for (int i = 0; i < 5; ++i)
            r[i] = gx4[tid + i * THREADS];
        #pragma unroll
        for (int i = 0; i < 5; ++i)
            sx4[tid + i * THREADS] = r[i];
        __syncthreads();

        // ---- compute: 2 rows per thread ----
        const int rA = row0 + tid;
        const int rB = rA + THREADS;
        const int dA = (dim_mask >= 0) ? (rA & dim_mask) : (rA % dim);
        const int dB = (dim_mask >= 0) ? (rB & dim_mask) : (rB % dim);
        process_row(sx, tid,           w, dA);
        process_row(sx, tid + THREADS, w, dB);
        __syncthreads();

        // ---- stage out ----
        float4* gy4 = reinterpret_cast<float4*>(y + base);
        #pragma unroll
        for (int i = 0; i < 5; ++i)
            gy4[tid + i * THREADS] = sx4[tid + i * THREADS];
    } else {
        // tail block (generic path)
        const int elems = rows_here * NPTS;
        for (int i = tid; i < elems; i += THREADS)
            sx[i] = x[base + i];
        __syncthreads();
        for (int rr = tid; rr < rows_here; rr += THREADS) {
            const int row = row0 + rr;
            const int d = (dim_mask >= 0) ? (row & dim_mask) : (row % dim);
            process_row(sx, rr, w, d);
        }
        __syncthreads();
        for (int i = tid; i < elems; i += THREADS)
            y[base + i] = sx[i];
    }
}

extern "C" void kernel_launch(void* const* d_in, const int* in_sizes, int n_in,
                              void* d_out, int out_size)
{
    const float* x = (const float*)d_in[0];
    const float* w = (const float*)d_in[1];
    float* y = (float*)d_out;

    const int n_rows = in_sizes[0] / NPTS;       // B * DIM
    const int dim    = in_sizes[1] / 12;         // DIM (6 freqs * 2)
    const int dim_mask = ((dim & (dim - 1)) == 0) ? (dim - 1) : -1;

    const int blocks = (n_rows + ROWS_PER_BLOCK - 1) / ROWS_PER_BLOCK;
    global_filter_kernel<<<blocks, THREADS>>>(x, w, y, n_rows, dim, dim_mask);
}

// round 5
// speedup vs baseline: 1.0132x; 1.0015x over previous
#include <cuda_runtime.h>
#include <cstdint>

// GlobalFilter: y = irfft(rfft(x, axis=-1) * w, n=10, axis=-1)
// x: [B, DIM, 10] f32, w: [DIM, 6, 2] f32 -> y: [B, DIM, 10] f32
// R4: persistent blocks, cp.async double-buffered 512-row tiles,
// split-radix N=10 closed form per row (2 rows/thread).

#define THREADS 256
#define TILE_ROWS 512
#define NPTS 10
#define TILE_ELEMS (TILE_ROWS * NPTS)     // 5120 floats = 20480 B
#define TILE_V4 (TILE_ELEMS / 4)          // 1280 float4 -> 5 per thread

__host__ __device__ constexpr float ctC(int j) {
    const float t[10] = {1.0f, 0.80901699437494745f, 0.30901699437494745f,
                         -0.30901699437494745f, -0.80901699437494745f, -1.0f,
                         -0.80901699437494745f, -0.30901699437494745f,
                         0.30901699437494745f, 0.80901699437494745f};
    return t[j % 10];
}
__host__ __device__ constexpr float ctS(int j) {
    const float t[10] = {0.0f, 0.58778525229247314f, 0.95105651629515353f,
                         0.95105651629515353f, 0.58778525229247314f, 0.0f,
                         -0.58778525229247314f, -0.95105651629515353f,
                         -0.95105651629515353f, -0.58778525229247314f};
    return t[j % 10];
}

__device__ __forceinline__ void cp_async16(uint32_t saddr, const void* gptr) {
    asm volatile("cp.async.cg.shared.global [%0], [%1], 16;"
                 :: "r"(saddr), "l"(gptr));
}
#define CP_COMMIT() asm volatile("cp.async.commit_group;" ::: "memory")
#define CP_WAIT0()  asm volatile("cp.async.wait_group 0;" ::: "memory")

// core 10-point filtered round-trip: xv -> yv, weights w0/w1/w2
__device__ __forceinline__ void dft10(const float xv[NPTS], float yv[NPTS],
                                      float4 w0, float4 w1, float4 w2)
{
    float u[5], v[5];
    #pragma unroll
    for (int s = 0; s < 5; ++s) {
        u[s] = xv[s] + xv[s + 5];
        v[s] = xv[s] - xv[s + 5];
    }
    float Xr0 = u[0] + u[1] + u[2] + u[3] + u[4];
    float Xr2 = u[0], Xi2 = 0.f, Xr4 = u[0], Xi4 = 0.f;
    #pragma unroll
    for (int s = 1; s < 5; ++s) {
        Xr2 += ctC(2 * s) * u[s];  Xi2 -= ctS(2 * s) * u[s];
        Xr4 += ctC(4 * s) * u[s];  Xi4 -= ctS(4 * s) * u[s];
    }
    float Xr1 = v[0], Xi1 = 0.f, Xr3 = v[0], Xi3 = 0.f;
    #pragma unroll
    for (int s = 1; s < 5; ++s) {
        Xr1 += ctC(1 * s) * v[s];  Xi1 -= ctS(1 * s) * v[s];
        Xr3 += ctC(3 * s) * v[s];  Xi3 -= ctS(3 * s) * v[s];
    }
    float Xr5 = v[0] - v[1] + v[2] - v[3] + v[4];

    const float a1 = w0.z, b1 = w0.w;
    const float a2 = w1.x, b2 = w1.y;
    const float a3 = w1.z, b3 = w1.w;
    const float a4 = w2.x, b4 = w2.y;
    const float Zr0 = 0.1f * (Xr0 * w0.x);
    const float Zr5 = 0.1f * (Xr5 * w2.z);
    const float zr1 = 0.2f * (Xr1 * a1 - Xi1 * b1);
    const float zi1 = 0.2f * (Xr1 * b1 + Xi1 * a1);
    const float zr2 = 0.2f * (Xr2 * a2 - Xi2 * b2);
    const float zi2 = 0.2f * (Xr2 * b2 + Xi2 * a2);
    const float zr3 = 0.2f * (Xr3 * a3 - Xi3 * b3);
    const float zi3 = 0.2f * (Xr3 * b3 + Xi3 * a3);
    const float zr4 = 0.2f * (Xr4 * a4 - Xi4 * b4);
    const float zi4 = 0.2f * (Xr4 * b4 + Xi4 * a4);

    #pragma unroll
    for (int t = 0; t < 5; ++t) {
        float E = Zr0
                + zr2 * ctC(2 * t) - zi2 * ctS(2 * t)
                + zr4 * ctC(4 * t) - zi4 * ctS(4 * t);
        float O = ((t & 1) ? -Zr5 : Zr5)
                + zr1 * ctC(t)     - zi1 * ctS(t)
                + zr3 * ctC(3 * t) - zi3 * ctS(3 * t);
        yv[t]     = E + O;
        yv[t + 5] = E - O;
    }
}

__device__ __forceinline__ void process_row(float* sx, int ridx,
                                            const float* __restrict__ w, int d)
{
    const float4* wp = reinterpret_cast<const float4*>(w + d * 12);
    const float4 w0 = wp[0];
    const float4 w1 = wp[1];
    const float4 w2 = wp[2];

    float xv[NPTS], yv[NPTS];
    const float2* s2 = reinterpret_cast<const float2*>(sx);
    #pragma unroll
    for (int i = 0; i < 5; ++i) {
        float2 p = s2[ridx * 5 + i];
        xv[2 * i] = p.x; xv[2 * i + 1] = p.y;
    }
    dft10(xv, yv, w0, w1, w2);
    float2* s2w = reinterpret_cast<float2*>(sx);
    #pragma unroll
    for (int i = 0; i < 5; ++i) {
        float2 p; p.x = yv[2 * i]; p.y = yv[2 * i + 1];
        s2w[ridx * 5 + i] = p;
    }
}

__global__ __launch_bounds__(THREADS)
void global_filter_kernel(const float* __restrict__ x,
                          const float* __restrict__ w,
                          float* __restrict__ y,
                          int n_rows, int dim, int dim_mask, int ntiles)
{
    __shared__ float sx[2][TILE_ELEMS];   // 40960 B

    const int tid    = threadIdx.x;
    const int stride = gridDim.x;
    int t = blockIdx.x;
    int parity = 0;

    uint32_t sbase[2];
    sbase[0] = (uint32_t)__cvta_generic_to_shared(&sx[0][0]);
    sbase[1] = (uint32_t)__cvta_generic_to_shared(&sx[1][0]);

    // ---- preamble: prefetch first tile ----
    if (t < ntiles) {
        const bool full = (long long)(t + 1) * TILE_ROWS <= (long long)n_rows;
        if (full) {
            const float4* g = reinterpret_cast<const float4*>(x) +
                              (long long)t * TILE_V4;
            #pragma unroll
            for (int i = 0; i < 5; ++i)
                cp_async16(sbase[0] + (uint32_t)(tid + i * THREADS) * 16u,
                           g + tid + i * THREADS);
        }
        CP_COMMIT();
    }

    for (; t < ntiles; t += stride, parity ^= 1) {
        const bool full = (long long)(t + 1) * TILE_ROWS <= (long long)n_rows;

        CP_WAIT0();            // current tile's data resident in sx[parity]
        __syncthreads();       // visible to all; prior stage-out reads of
                               // sx[parity^1] also completed before this point

        // ---- prefetch tile t+stride into the other buffer ----
        const int tn = t + stride;
        if (tn < ntiles) {
            const bool fulln = (long long)(tn + 1) * TILE_ROWS <= (long long)n_rows;
            if (fulln) {
                const float4* g = reinterpret_cast<const float4*>(x) +
                                  (long long)tn * TILE_V4;
                #pragma unroll
                for (int i = 0; i < 5; ++i)
                    cp_async16(sbase[parity ^ 1] + (uint32_t)(tid + i * THREADS) * 16u,
                               g + tid + i * THREADS);
            }
            CP_COMMIT();
        }

        if (full) {
            // ---- compute: 2 rows per thread, in place ----
            const int rA = t * TILE_ROWS + tid;
            const int rB = rA + THREADS;
            const int dA = (dim_mask >= 0) ? (rA & dim_mask) : (rA % dim);
            const int dB = (dim_mask >= 0) ? (rB & dim_mask) : (rB % dim);
            process_row(sx[parity], tid,           w, dA);
            process_row(sx[parity], tid + THREADS, w, dB);
            __syncthreads();

            // ---- stage out (coalesced float4) ----
            float4* gy = reinterpret_cast<float4*>(y) + (long long)t * TILE_V4;
            const float4* s4 = reinterpret_cast<const float4*>(sx[parity]);
            #pragma unroll
            for (int i = 0; i < 5; ++i)
                gy[tid + i * THREADS] = s4[tid + i * THREADS];
        } else {
            // ---- tail tile: straight from global, scalar ----
            const int rows_here = n_rows - t * TILE_ROWS;
            for (int rr = tid; rr < rows_here; rr += THREADS) {
                const int row = t * TILE_ROWS + rr;
                const long long rb = (long long)row * NPTS;
                const int d = (dim_mask >= 0) ? (row & dim_mask) : (row % dim);
                const float4* wp = reinterpret_cast<const float4*>(w + d * 12);
                float xv[NPTS], yv[NPTS];
                #pragma unroll
                for (int i = 0; i < NPTS; ++i) xv[i] = x[rb + i];
                dft10(xv, yv, wp[0], wp[1], wp[2]);
                #pragma unroll
                for (int i = 0; i < NPTS; ++i) y[rb + i] = yv[i];
            }
            __syncthreads();
        }
    }
}

extern "C" void kernel_launch(void* const* d_in, const int* in_sizes, int n_in,
                              void* d_out, int out_size)
{
    const float* x = (const float*)d_in[0];
    const float* w = (const float*)d_in[1];
    float* y = (float*)d_out;

    const int n_rows = in_sizes[0] / NPTS;       // B * DIM
    const int dim    = in_sizes[1] / 12;         // DIM
    const int dim_mask = ((dim & (dim - 1)) == 0) ? (dim - 1) : -1;
    const int ntiles = (n_rows + TILE_ROWS - 1) / TILE_ROWS;

    // persistent grid: exactly the resident-block count
    static int blocks_per_sm = 0, num_sms = 0;
    if (blocks_per_sm == 0) {
        cudaOccupancyMaxActiveBlocksPerMultiprocessor(
            &blocks_per_sm, global_filter_kernel, THREADS, 0);
        cudaDeviceGetAttribute(&num_sms, cudaDevAttrMultiProcessorCount, 0);
        if (blocks_per_sm <= 0) blocks_per_sm = 5;
        if (num_sms <= 0) num_sms = 148;
    }
    int grid = blocks_per_sm * num_sms;
    if (grid > ntiles) grid = ntiles;

    global_filter_kernel<<<grid, THREADS>>>(x, w, y, n_rows, dim, dim_mask, ntiles);
}